// round 2
// baseline (speedup 1.0000x reference)
#include <cuda_runtime.h>
#include <cstdint>

// NeRF positional encoding:
//   x:   [rows, 4]   float32   (rows = 64*1024)
//   out: [rows, 768] float32
// out[row, k*64 + L*8 + 2c + s] = (s==0 ? sin : cos)(2^L * pi * x[row,c])
//
// R1 strategy: stage each block's 8 contiguous rows (24 KB) in shared memory
// via STS.128, then issue ONE cp.async.bulk (TMA bulk engine) shared->global
// per block. This removes the STG.128 issue cost (12 cyc each, ~55% of SM
// cycles in R0) and the L1tex global-store wavefronts from the critical path.

#define ROWS_PER_BLK 8   // 8 rows x 3072 B = 24 KB smem -> 9 blocks/SM resident

__global__ void __launch_bounds__(256)
nerf_pe_tma_kernel(const float4* __restrict__ x, float4* __restrict__ out, int rows) {
    __shared__ __align__(128) float4 buf[ROWS_PER_BLK * 192];   // 24 KB

    const int warpid = threadIdx.x >> 5;       // one warp per row
    const int lane   = threadIdx.x & 31;
    const int base   = blockIdx.x * ROWS_PER_BLK;
    const int row    = base + warpid;

    if (row < rows) {
        // Broadcast 16B load of this row's 4 coords
        const float4 xv = __ldg(&x[row]);

        const int q = lane & 15;               // 0..15: (L = q>>1, coord pair = q&1)
        const int h = lane >> 4;               // repetition parity
        const int L = q >> 1;

        // 2^L * pi: exact power-of-two scaling of f32 pi, matches reference
        const float f = 3.14159265358979323846f * (float)(1 << L);
        const float a = (q & 1) ? xv.z : xv.x;
        const float b = (q & 1) ? xv.w : xv.y;

        float s0, c0, s1, c1;
        sincosf(f * a, &s0, &c0);
        sincosf(f * b, &s1, &c1);
        const float4 v = make_float4(s0, c0, s1, c1);

        // Row = 192 float4. Rep r occupies float4 [r*16, r*16+16).
        float4* o = buf + warpid * 192 + h * 16 + q;
        #pragma unroll
        for (int r = 0; r < 6; ++r)
            o[r * 32] = v;                     // STS.128, conflict-free
    }
    __syncthreads();

    const int nrow = min(ROWS_PER_BLK, rows - base);
    if (nrow > 0 && threadIdx.x == 0) {
        // Order the generic-proxy STS above before the async-proxy bulk read
        asm volatile("fence.proxy.async.shared::cta;" ::: "memory");

        uint32_t src   = (uint32_t)__cvta_generic_to_shared(buf);
        uint64_t dst   = (uint64_t)(out + (size_t)base * 192);
        uint32_t bytes = (uint32_t)nrow * 3072u;

        asm volatile(
            "cp.async.bulk.global.shared::cta.bulk_group [%0], [%1], %2;"
            :: "l"(dst), "r"(src), "r"(bytes) : "memory");
        asm volatile("cp.async.bulk.commit_group;" ::: "memory");
        // Hold block retirement until the bulk engine is done with smem + GMEM
        asm volatile("cp.async.bulk.wait_group 0;" ::: "memory");
    }
}

extern "C" void kernel_launch(void* const* d_in, const int* in_sizes, int n_in,
                              void* d_out, int out_size) {
    const float4* x = (const float4*)d_in[0];
    float4* out = (float4*)d_out;
    const int rows = in_sizes[0] / 4;          // [rows, 4] coords

    const int blocks = (rows + ROWS_PER_BLK - 1) / ROWS_PER_BLK;
    nerf_pe_tma_kernel<<<blocks, 256>>>(x, out, rows);
}